// round 3
// baseline (speedup 1.0000x reference)
#include <cuda_runtime.h>
#include <cuda_bf16.h>
#include <cstdint>
#include <cstdio>

#define BB 2
#define SS 2048
#define HIST 2048
#define NH 16
#define HD 128
#define DIM 2048
#define LL (HIST + SS)   // 4096

// ---------------- scratch (no allocations allowed) ----------------
__device__ __align__(16) float g_xq[(size_t)BB * SS * DIM];     // 33.5 MB
__device__ __align__(16) float g_attn[(size_t)BB * SS * DIM];   // 33.5 MB
__device__ __align__(16) float g_kall[(size_t)BB * LL * DIM];   // 67 MB
__device__ __align__(16) float g_vall[(size_t)BB * LL * DIM];   // 67 MB

// ---------------- copy history into k_all/v_all ----------------
__global__ void copy_hist_kernel(const float4* __restrict__ pk,
                                 const float4* __restrict__ pv,
                                 float4* __restrict__ kall,
                                 float4* __restrict__ vall) {
    const size_t n = (size_t)BB * HIST * DIM / 4;
    const size_t rowlen = DIM / 4;  // 512 float4 per row
    for (size_t i = (size_t)blockIdx.x * blockDim.x + threadIdx.x; i < n;
         i += (size_t)gridDim.x * blockDim.x) {
        size_t row = i / rowlen;          // b*HIST + t
        size_t b = row / HIST;
        size_t t = row % HIST;
        size_t c = i % rowlen;
        size_t dst = ((b * LL + t) * rowlen) + c;
        kall[dst] = pk[i];
        vall[dst] = pv[i];
    }
}

// ---------------- export k_all/v_all to d_out ----------------
__global__ void export_kv_kernel(const float4* __restrict__ kall,
                                 const float4* __restrict__ vall,
                                 float4* __restrict__ dk,
                                 float4* __restrict__ dv) {
    const size_t n = (size_t)BB * LL * DIM / 4;
    for (size_t i = (size_t)blockIdx.x * blockDim.x + threadIdx.x; i < n;
         i += (size_t)gridDim.x * blockDim.x) {
        dk[i] = kall[i];
        dv[i] = vall[i];
    }
}

// ---------------- SGEMM: C[rm(m)][n] = sum_k A[m][k] * W[n][k] ----------------
// A: [M,K] row-major. W: [N,K] row-major (i.e., Y = A @ W^T).
// kvmode=0: output row = m. kvmode=1: output row = m + HIST*(m/SS + 1)
// (scatters xk/xv rows into the k_all [B, L, HK, D] layout).
__global__ __launch_bounds__(256, 2) void sgemm_nt_kernel(
    const float* __restrict__ A, const float* __restrict__ W,
    float* __restrict__ C, int M, int N, int K, int kvmode) {
    __shared__ __align__(16) float As[16][132];
    __shared__ __align__(16) float Bs[16][132];

    const int bm = blockIdx.y * 128;
    const int bn = blockIdx.x * 128;
    const int tid = threadIdx.x;
    const int tm = tid >> 4;   // 0..15
    const int tn = tid & 15;   // 0..15

    float acc[8][8];
#pragma unroll
    for (int i = 0; i < 8; ++i)
#pragma unroll
        for (int j = 0; j < 8; ++j) acc[i][j] = 0.f;

    for (int k0 = 0; k0 < K; k0 += 16) {
        __syncthreads();
#pragma unroll
        for (int l = tid; l < 512; l += 256) {
            int r = l >> 2;
            int c4 = (l & 3) << 2;
            float4 av = *(const float4*)&A[(size_t)(bm + r) * K + k0 + c4];
            As[c4 + 0][r] = av.x; As[c4 + 1][r] = av.y;
            As[c4 + 2][r] = av.z; As[c4 + 3][r] = av.w;
            float4 bv = *(const float4*)&W[(size_t)(bn + r) * K + k0 + c4];
            Bs[c4 + 0][r] = bv.x; Bs[c4 + 1][r] = bv.y;
            Bs[c4 + 2][r] = bv.z; Bs[c4 + 3][r] = bv.w;
        }
        __syncthreads();
#pragma unroll
        for (int kk = 0; kk < 16; ++kk) {
            float4 a0 = *(const float4*)&As[kk][tm * 8];
            float4 a1 = *(const float4*)&As[kk][tm * 8 + 4];
            float4 b0 = *(const float4*)&Bs[kk][tn * 8];
            float4 b1 = *(const float4*)&Bs[kk][tn * 8 + 4];
            float ar[8] = {a0.x, a0.y, a0.z, a0.w, a1.x, a1.y, a1.z, a1.w};
            float br[8] = {b0.x, b0.y, b0.z, b0.w, b1.x, b1.y, b1.z, b1.w};
#pragma unroll
            for (int i = 0; i < 8; ++i)
#pragma unroll
                for (int j = 0; j < 8; ++j) acc[i][j] += ar[i] * br[j];
        }
    }

#pragma unroll
    for (int i = 0; i < 8; ++i) {
        int m = bm + tm * 8 + i;
        size_t orow = kvmode ? ((size_t)m + (size_t)HIST * ((m / SS) + 1))
                             : (size_t)m;
        float4 c0 = make_float4(acc[i][0], acc[i][1], acc[i][2], acc[i][3]);
        float4 c1 = make_float4(acc[i][4], acc[i][5], acc[i][6], acc[i][7]);
        *(float4*)&C[orow * N + bn + tn * 8] = c0;
        *(float4*)&C[orow * N + bn + tn * 8 + 4] = c1;
    }
}

// ---------------- flash attention (fp32) ----------------
// grid: (S/64, NH, B); block: 256 threads (tx = tid&15, ty = tid>>4)
// Each thread: 4 q-rows (ty*4+i), S-cols kj = tx+16j, O-cols dd = tx*8..+7.
#define ATTN_SMEM_FLOATS (64 * 132 + 64 * 128 + 64 * 68)
#define ATTN_SMEM_BYTES (ATTN_SMEM_FLOATS * 4)

__global__ __launch_bounds__(256, 2) void attn_kernel(
    const float* __restrict__ q, const float* __restrict__ kall,
    const float* __restrict__ vall, float* __restrict__ o) {
    extern __shared__ __align__(16) float sm[];
    float* Qs = sm;                  // [64][132] row-major, padded
    float* KVs = sm + 64 * 132;      // [64][128] float4-XOR swizzled
    float* Ps = KVs + 64 * 128;      // [64][68]

    const int qt = blockIdx.x, h = blockIdx.y, b = blockIdx.z;
    const int q0 = qt * 64;
    const int tid = threadIdx.x;
    const int tx = tid & 15, ty = tid >> 4;

    // load Q tile [64][128]
#pragma unroll
    for (int l = tid; l < 64 * 32; l += 256) {
        int r = l >> 5, c4 = l & 31;
        float4 v = *(const float4*)&q[((size_t)(b * SS + q0 + r)) * DIM +
                                      h * HD + c4 * 4];
        *(float4*)&Qs[r * 132 + c4 * 4] = v;
    }

    float m_run[4], l_run[4], oacc[4][8];
#pragma unroll
    for (int i = 0; i < 4; ++i) {
        m_run[i] = -1e30f;
        l_run[i] = 0.f;
#pragma unroll
        for (int d = 0; d < 8; ++d) oacc[i][d] = 0.f;
    }

    const float SCALE = 0.08838834764831845f;  // 1/sqrt(128)
    const int nt = (HIST + q0 + 64) >> 6;      // number of 64-wide k tiles

    for (int t = 0; t < nt; ++t) {
        const int k0 = t << 6;
        __syncthreads();  // previous V reads done before overwriting KVs
        // load K tile [64][128] with XOR swizzle
#pragma unroll
        for (int l = tid; l < 64 * 32; l += 256) {
            int r = l >> 5, c4 = l & 31;
            float4 v = *(const float4*)&kall[((size_t)(b * LL + k0 + r)) * DIM +
                                             h * HD + c4 * 4];
            ((float4*)KVs)[r * 32 + (c4 ^ (r & 31))] = v;
        }
        __syncthreads();

        // S = Q K^T (thread: rows ty*4+i, cols tx+16j)
        float acc[4][4];
#pragma unroll
        for (int i = 0; i < 4; ++i)
#pragma unroll
            for (int j = 0; j < 4; ++j) acc[i][j] = 0.f;

#pragma unroll 4
        for (int kk4 = 0; kk4 < 32; ++kk4) {
            float4 qv[4];
#pragma unroll
            for (int i = 0; i < 4; ++i)
                qv[i] = *(const float4*)&Qs[(ty * 4 + i) * 132 + kk4 * 4];
#pragma unroll
            for (int j = 0; j < 4; ++j) {
                int r = tx + (j << 4);
                float4 kv = ((const float4*)KVs)[r * 32 + (kk4 ^ (r & 31))];
#pragma unroll
                for (int i = 0; i < 4; ++i)
                    acc[i][j] += qv[i].x * kv.x + qv[i].y * kv.y +
                                 qv[i].z * kv.z + qv[i].w * kv.w;
            }
        }

        // scale + causal mask (only last tile can be masked)
        const bool need_mask = (k0 + 63 > HIST + q0);
#pragma unroll
        for (int i = 0; i < 4; ++i)
#pragma unroll
            for (int j = 0; j < 4; ++j) {
                float s = acc[i][j] * SCALE;
                if (need_mask) {
                    int kg = k0 + tx + (j << 4);
                    int qg = q0 + ty * 4 + i;
                    if (kg > HIST + qg) s = -1e30f;
                }
                acc[i][j] = s;
            }

        // online softmax; row shared by 16 lanes (same ty) -> width-16 shfl
#pragma unroll
        for (int i = 0; i < 4; ++i) {
            float mx = fmaxf(fmaxf(acc[i][0], acc[i][1]),
                             fmaxf(acc[i][2], acc[i][3]));
#pragma unroll
            for (int off = 8; off; off >>= 1)
                mx = fmaxf(mx, __shfl_xor_sync(0xffffffffu, mx, off, 16));
            float mnew = fmaxf(m_run[i], mx);
            float corr = __expf(m_run[i] - mnew);
            float psum = 0.f;
#pragma unroll
            for (int j = 0; j < 4; ++j) {
                float p = __expf(acc[i][j] - mnew);
                acc[i][j] = p;
                psum += p;
            }
#pragma unroll
            for (int off = 8; off; off >>= 1)
                psum += __shfl_xor_sync(0xffffffffu, psum, off, 16);
            l_run[i] = l_run[i] * corr + psum;
            m_run[i] = mnew;
#pragma unroll
            for (int d = 0; d < 8; ++d) oacc[i][d] *= corr;
#pragma unroll
            for (int j = 0; j < 4; ++j)
                Ps[(ty * 4 + i) * 68 + tx + (j << 4)] = acc[i][j];
        }
        __syncthreads();  // S-phase K reads + Ps writes complete

        // load V tile over KVs (same swizzle)
#pragma unroll
        for (int l = tid; l < 64 * 32; l += 256) {
            int r = l >> 5, c4 = l & 31;
            float4 v = *(const float4*)&vall[((size_t)(b * LL + k0 + r)) * DIM +
                                             h * HD + c4 * 4];
            ((float4*)KVs)[r * 32 + (c4 ^ (r & 31))] = v;
        }
        __syncthreads();

        // O += P @ V  (thread: rows ty*4+i, logical cols 8tx..8tx+7)
#pragma unroll 4
        for (int j = 0; j < 64; ++j) {
            float4 v0 = ((const float4*)KVs)[j * 32 + ((tx * 2) ^ (j & 31))];
            float4 v1 = ((const float4*)KVs)[j * 32 + ((tx * 2 + 1) ^ (j & 31))];
            float pr[4];
#pragma unroll
            for (int i = 0; i < 4; ++i) pr[i] = Ps[(ty * 4 + i) * 68 + j];
#pragma unroll
            for (int i = 0; i < 4; ++i) {
                oacc[i][0] += pr[i] * v0.x;
                oacc[i][1] += pr[i] * v0.y;
                oacc[i][2] += pr[i] * v0.z;
                oacc[i][3] += pr[i] * v0.w;
                oacc[i][4] += pr[i] * v1.x;
                oacc[i][5] += pr[i] * v1.y;
                oacc[i][6] += pr[i] * v1.z;
                oacc[i][7] += pr[i] * v1.w;
            }
        }
    }

    // epilogue: normalize and store
#pragma unroll
    for (int i = 0; i < 4; ++i) {
        float inv = 1.f / l_run[i];
        float4 r0 = make_float4(oacc[i][0] * inv, oacc[i][1] * inv,
                                oacc[i][2] * inv, oacc[i][3] * inv);
        float4 r1 = make_float4(oacc[i][4] * inv, oacc[i][5] * inv,
                                oacc[i][6] * inv, oacc[i][7] * inv);
        size_t base =
            ((size_t)(b * SS + q0 + ty * 4 + i)) * DIM + h * HD + tx * 8;
        *(float4*)&o[base] = r0;
        *(float4*)&o[base + 4] = r1;
    }
}

// ---------------- launch ----------------
extern "C" void kernel_launch(void* const* d_in, const int* in_sizes, int n_in,
                              void* d_out, int out_size) {
    const float* x = (const float*)d_in[0];
    const float* prev_k = (const float*)d_in[1];
    const float* prev_v = (const float*)d_in[2];
    // d_in[3] = mask (computed analytically, unused)
    const float* wq = (const float*)d_in[4];
    const float* wk = (const float*)d_in[5];
    const float* wv = (const float*)d_in[6];
    const float* wo = (const float*)d_in[7];

    float* out = (float*)d_out;
    const size_t OUT_ELEMS = (size_t)BB * SS * DIM;       //  8,388,608
    const size_t KV_ELEMS = (size_t)BB * LL * NH * HD;    // 16,777,216

    float* xq;    cudaGetSymbolAddress((void**)&xq, g_xq);
    float* attn;  cudaGetSymbolAddress((void**)&attn, g_attn);
    float* kall;  cudaGetSymbolAddress((void**)&kall, g_kall);
    float* vall;  cudaGetSymbolAddress((void**)&vall, g_vall);

    // 1) history copy into scratch k_all/v_all
    copy_hist_kernel<<<1024, 256>>>((const float4*)prev_k,
                                    (const float4*)prev_v, (float4*)kall,
                                    (float4*)vall);

    // 2) projections: xq -> scratch; xk/xv scattered into k_all/v_all tails
    dim3 gproj(DIM / 128, (BB * SS) / 128);  // (16, 32)
    sgemm_nt_kernel<<<gproj, 256>>>(x, wq, xq, BB * SS, DIM, DIM, 0);
    sgemm_nt_kernel<<<gproj, 256>>>(x, wk, kall, BB * SS, DIM, DIM, 1);
    sgemm_nt_kernel<<<gproj, 256>>>(x, wv, vall, BB * SS, DIM, DIM, 1);

    // 3) attention
    cudaFuncSetAttribute(attn_kernel,
                         cudaFuncAttributeMaxDynamicSharedMemorySize,
                         ATTN_SMEM_BYTES);
    attn_kernel<<<dim3(SS / 64, NH, BB), 256, ATTN_SMEM_BYTES>>>(xq, kall,
                                                                 vall, attn);

    // 4) output projection -> d_out[0 : B*S*DIM]
    sgemm_nt_kernel<<<gproj, 256>>>(attn, wo, out, BB * SS, DIM, DIM, 0);

    // 5) export k_all / v_all if the harness expects the full tuple
    if ((size_t)out_size >= OUT_ELEMS + 2 * KV_ELEMS) {
        float* dk = out + OUT_ELEMS;
        float* dv = dk + KV_ELEMS;
        export_kv_kernel<<<2048, 256>>>((const float4*)kall,
                                        (const float4*)vall, (float4*)dk,
                                        (float4*)dv);
    }
}

// round 4
// speedup vs baseline: 1.7803x; 1.7803x over previous
#include <cuda_runtime.h>
#include <cuda_bf16.h>
#include <cstdint>

#define BB 2
#define SS 2048
#define HIST 2048
#define NH 16
#define HD 128
#define DIM 2048
#define LL (HIST + SS)   // 4096

// ---------------- scratch (no allocations allowed) ----------------
__device__ __align__(16) float g_xq[(size_t)BB * SS * DIM];     // 33.5 MB
__device__ __align__(16) float g_attn[(size_t)BB * SS * DIM];   // 33.5 MB
__device__ __align__(16) float g_kall[(size_t)BB * LL * DIM];   // 67 MB
__device__ __align__(16) float g_vall[(size_t)BB * LL * DIM];   // 67 MB

// ---------------- helpers ----------------
__device__ __forceinline__ uint32_t f2tf(float f) {
    uint32_t u;
    asm("cvt.rna.tf32.f32 %0, %1;" : "=r"(u) : "f"(f));
    return u;
}

__device__ __forceinline__ void mma_tf32(float* c, uint32_t a0, uint32_t a1,
                                         uint32_t a2, uint32_t a3, uint32_t b0,
                                         uint32_t b1) {
    asm volatile(
        "mma.sync.aligned.m16n8k8.row.col.f32.tf32.tf32.f32 "
        "{%0,%1,%2,%3}, {%4,%5,%6,%7}, {%8,%9}, {%0,%1,%2,%3};"
        : "+f"(c[0]), "+f"(c[1]), "+f"(c[2]), "+f"(c[3])
        : "r"(a0), "r"(a1), "r"(a2), "r"(a3), "r"(b0), "r"(b1));
}

// ---------------- copy history into k_all/v_all ----------------
__global__ void copy_hist_kernel(const float4* __restrict__ pk,
                                 const float4* __restrict__ pv,
                                 float4* __restrict__ kall,
                                 float4* __restrict__ vall) {
    const size_t n = (size_t)BB * HIST * DIM / 4;
    const size_t rowlen = DIM / 4;
    for (size_t i = (size_t)blockIdx.x * blockDim.x + threadIdx.x; i < n;
         i += (size_t)gridDim.x * blockDim.x) {
        size_t row = i / rowlen;
        size_t b = row / HIST;
        size_t t = row % HIST;
        size_t c = i % rowlen;
        size_t dst = ((b * LL + t) * rowlen) + c;
        kall[dst] = pk[i];
        vall[dst] = pv[i];
    }
}

// ---------------- export k_all/v_all to d_out ----------------
__global__ void export_kv_kernel(const float4* __restrict__ kall,
                                 const float4* __restrict__ vall,
                                 float4* __restrict__ dk,
                                 float4* __restrict__ dv) {
    const size_t n = (size_t)BB * LL * DIM / 4;
    for (size_t i = (size_t)blockIdx.x * blockDim.x + threadIdx.x; i < n;
         i += (size_t)gridDim.x * blockDim.x) {
        dk[i] = kall[i];
        dv[i] = vall[i];
    }
}

// ---------------- tf32 GEMM: C[rm(m)][n] = sum_k A[m][k] * W[n][k] -----------
// A: [4096, 2048] row-major, W: [2048, 2048] row-major (Y = A @ W^T).
// Block 128x128, BK=16, 8 warps as 2x4 -> warp tile 64x32.
// Operands staged in smem in mma fragment layout (tf32 bits).
__global__ __launch_bounds__(256, 2) void gemm_tf32_kernel(
    const float* __restrict__ A, const float* __restrict__ W,
    float* __restrict__ C, int kvmode) {
    __shared__ uint32_t As[2048];  // [(mt*2+kt)*128 + lane*4 + reg]
    __shared__ uint32_t Bs[2048];  // [(nt*2+kt)*64 + lane*2 + reg]

    const int bm = blockIdx.y * 128, bn = blockIdx.x * 128;
    const int tid = threadIdx.x;
    const int w = tid >> 5, lane = tid & 31;
    const int wm = w >> 2, wn = w & 3;
    const int g = lane >> 2, tg = lane & 3;

    float acc[4][4][4];
#pragma unroll
    for (int mt = 0; mt < 4; ++mt)
#pragma unroll
        for (int nt = 0; nt < 4; ++nt)
#pragma unroll
            for (int e = 0; e < 4; ++e) acc[mt][nt][e] = 0.f;

    float4 ra[2], rb[2];
#pragma unroll
    for (int i = 0; i < 2; ++i) {
        int l = tid + (i << 8);
        int r = l >> 2, c4 = l & 3;
        ra[i] = *(const float4*)&A[(size_t)(bm + r) * DIM + (c4 << 2)];
        rb[i] = *(const float4*)&W[(size_t)(bn + r) * DIM + (c4 << 2)];
    }

    for (int k0 = 0; k0 < DIM; k0 += 16) {
#pragma unroll
        for (int i = 0; i < 2; ++i) {
            int l = tid + (i << 8);
            int r = l >> 2, c4 = l & 3;
            int kt = c4 >> 1, khi = c4 & 1;
            // A frag: lane=(r&7)*4+e, reg=((r&15)>=8)+2*khi
            uint32_t* da = &As[(((r >> 4) << 1) + kt) * 128 + ((r & 7) << 4) +
                               ((r & 15) >> 3) + (khi << 1)];
            da[0] = f2tf(ra[i].x);
            da[4] = f2tf(ra[i].y);
            da[8] = f2tf(ra[i].z);
            da[12] = f2tf(ra[i].w);
            // B frag: lane=(r&7)*4+e, reg=khi
            uint32_t* db =
                &Bs[(((r >> 3) << 1) + kt) * 64 + ((r & 7) << 3) + khi];
            db[0] = f2tf(rb[i].x);
            db[2] = f2tf(rb[i].y);
            db[4] = f2tf(rb[i].z);
            db[6] = f2tf(rb[i].w);
        }
        __syncthreads();

        if (k0 + 16 < DIM) {
#pragma unroll
            for (int i = 0; i < 2; ++i) {
                int l = tid + (i << 8);
                int r = l >> 2, c4 = l & 3;
                ra[i] = *(const float4*)&A[(size_t)(bm + r) * DIM + k0 + 16 +
                                           (c4 << 2)];
                rb[i] = *(const float4*)&W[(size_t)(bn + r) * DIM + k0 + 16 +
                                           (c4 << 2)];
            }
        }

#pragma unroll
        for (int kt = 0; kt < 2; ++kt) {
            uint4 av[4];
            uint2 bv[4];
#pragma unroll
            for (int mt = 0; mt < 4; ++mt)
                av[mt] = *(const uint4*)&As[(((wm * 4 + mt) << 1) + kt) * 128 +
                                            (lane << 2)];
#pragma unroll
            for (int nt = 0; nt < 4; ++nt)
                bv[nt] = *(const uint2*)&Bs[(((wn * 4 + nt) << 1) + kt) * 64 +
                                            (lane << 1)];
#pragma unroll
            for (int mt = 0; mt < 4; ++mt)
#pragma unroll
                for (int nt = 0; nt < 4; ++nt)
                    mma_tf32(acc[mt][nt], av[mt].x, av[mt].y, av[mt].z,
                             av[mt].w, bv[nt].x, bv[nt].y);
        }
        __syncthreads();
    }

#pragma unroll
    for (int mt = 0; mt < 4; ++mt)
#pragma unroll
        for (int nt = 0; nt < 4; ++nt)
#pragma unroll
            for (int hh = 0; hh < 2; ++hh) {
                int m = bm + (wm * 4 + mt) * 16 + g + hh * 8;
                size_t orow = kvmode
                                  ? ((size_t)m + (size_t)HIST * ((m >> 11) + 1))
                                  : (size_t)m;
                int col = bn + (wn * 4 + nt) * 8 + (tg << 1);
                *(float2*)&C[orow * DIM + col] =
                    make_float2(acc[mt][nt][hh * 2], acc[mt][nt][hh * 2 + 1]);
            }
}

// ---------------- flash attention (tf32 mma) ----------------
// Q tile 128 x k tile 64, D=128. 8 warps; warp w owns q-rows [w*16, w*16+16).
// Smem (tf32 fragment layouts):
//   Qs: 128x128 A-frag (pre-scaled), Ks: 64x128 B-frag,
//   Vs: 64x128 B-frag, Ps: 128x64 A-frag (warp-private regions).
#define ATTN_SMEM_UINTS (16384 + 8192 + 8192 + 8192)
#define ATTN_SMEM_BYTES (ATTN_SMEM_UINTS * 4)

__global__ __launch_bounds__(256, 1) void attn_mma_kernel(
    const float* __restrict__ q, const float* __restrict__ kall,
    const float* __restrict__ vall, float* __restrict__ o) {
    extern __shared__ uint32_t smu[];
    uint32_t* Qs = smu;
    uint32_t* Ks = smu + 16384;
    uint32_t* Vs = Ks + 8192;
    uint32_t* Ps = Vs + 8192;

    const int qt = gridDim.x - 1 - blockIdx.x;  // heavy blocks first
    const int h = blockIdx.y, b = blockIdx.z;
    const int q0 = qt * 128;
    const int tid = threadIdx.x;
    const int w = tid >> 5, lane = tid & 31, g = lane >> 2, tg = lane & 3;
    const float SCALE = 0.08838834764831845f;  // 1/sqrt(128)

    // stage Q (scaled, A-frag layout)
#pragma unroll 4
    for (int l = tid; l < 128 * 32; l += 256) {
        int r = l >> 5, c4 = l & 31;
        float4 v = *(const float4*)&q[((size_t)(b * SS + q0 + r)) * DIM +
                                      h * HD + (c4 << 2)];
        int base = (((r >> 4) << 4) + (c4 >> 1)) * 128 + ((r & 7) << 4) +
                   ((r & 15) >> 3) + ((c4 & 1) << 1);
        Qs[base + 0] = f2tf(v.x * SCALE);
        Qs[base + 4] = f2tf(v.y * SCALE);
        Qs[base + 8] = f2tf(v.z * SCALE);
        Qs[base + 12] = f2tf(v.w * SCALE);
    }

    float oacc[16][4];
#pragma unroll
    for (int dt = 0; dt < 16; ++dt)
#pragma unroll
        for (int e = 0; e < 4; ++e) oacc[dt][e] = 0.f;
    float mrun[2] = {-1e30f, -1e30f}, lrun[2] = {0.f, 0.f};

    const int ntile = (HIST + q0 + 128) >> 6;
    for (int t = 0; t < ntile; ++t) {
        const int k0 = t << 6;
        __syncthreads();  // prior S/O reads of Ks/Vs complete (also covers Qs)

        // stage K (B-frag for S) and V (B-frag for O)
#pragma unroll 2
        for (int l = tid; l < 64 * 32; l += 256) {
            int r = l >> 5, c4 = l & 31;
            const size_t grow =
                ((size_t)(b * LL + k0 + r)) * DIM + h * HD + (c4 << 2);
            float4 kv = *(const float4*)&kall[grow];
            int bK = (((r >> 3) << 4) + (c4 >> 1)) * 64 + ((r & 7) << 3) +
                     (c4 & 1);
            Ks[bK + 0] = f2tf(kv.x);
            Ks[bK + 2] = f2tf(kv.y);
            Ks[bK + 4] = f2tf(kv.z);
            Ks[bK + 6] = f2tf(kv.w);
            float4 vv = *(const float4*)&vall[grow];
            int bV = (((c4 >> 1) << 3) + (r >> 3)) * 64 +
                     (((c4 & 1) << 4) + (r & 3)) * 2 + ((r >> 2) & 1);
            Vs[bV + 0] = f2tf(vv.x);
            Vs[bV + 8] = f2tf(vv.y);
            Vs[bV + 16] = f2tf(vv.z);
            Vs[bV + 24] = f2tf(vv.w);
        }
        __syncthreads();

        // S = Q K^T : warp tile m16 x n64, k=128
        float sacc[8][4];
#pragma unroll
        for (int nt = 0; nt < 8; ++nt)
#pragma unroll
            for (int e = 0; e < 4; ++e) sacc[nt][e] = 0.f;
#pragma unroll
        for (int kt = 0; kt < 16; ++kt) {
            uint4 av = *(const uint4*)&Qs[((w << 4) + kt) * 128 + (lane << 2)];
#pragma unroll
            for (int nt = 0; nt < 8; ++nt) {
                uint2 bv =
                    *(const uint2*)&Ks[((nt << 4) + kt) * 64 + (lane << 1)];
                mma_tf32(sacc[nt], av.x, av.y, av.z, av.w, bv.x, bv.y);
            }
        }

        // causal mask (scores already scaled via Q)
        if (k0 + 63 > HIST + q0 + (w << 4)) {
#pragma unroll
            for (int nt = 0; nt < 8; ++nt)
#pragma unroll
                for (int e = 0; e < 4; ++e) {
                    int kg = k0 + (nt << 3) + (tg << 1) + (e & 1);
                    int qg = q0 + (w << 4) + g + ((e >> 1) << 3);
                    if (kg > HIST + qg) sacc[nt][e] = -1e30f;
                }
        }

        // online softmax; rows g (regs 0,1) and g+8 (regs 2,3)
#pragma unroll
        for (int hh = 0; hh < 2; ++hh) {
            float mx = -1e30f;
#pragma unroll
            for (int nt = 0; nt < 8; ++nt)
                mx = fmaxf(mx, fmaxf(sacc[nt][hh * 2], sacc[nt][hh * 2 + 1]));
            mx = fmaxf(mx, __shfl_xor_sync(0xffffffffu, mx, 1, 4));
            mx = fmaxf(mx, __shfl_xor_sync(0xffffffffu, mx, 2, 4));
            float mnew = fmaxf(mrun[hh], mx);
            float corr = __expf(mrun[hh] - mnew);
            float rs = 0.f;
#pragma unroll
            for (int nt = 0; nt < 8; ++nt) {
                float p0 = __expf(sacc[nt][hh * 2] - mnew);
                float p1 = __expf(sacc[nt][hh * 2 + 1] - mnew);
                sacc[nt][hh * 2] = p0;
                sacc[nt][hh * 2 + 1] = p1;
                rs += p0 + p1;
            }
            rs += __shfl_xor_sync(0xffffffffu, rs, 1, 4);
            rs += __shfl_xor_sync(0xffffffffu, rs, 2, 4);
            lrun[hh] = lrun[hh] * corr + rs;
            mrun[hh] = mnew;
#pragma unroll
            for (int dt = 0; dt < 16; ++dt) {
                oacc[dt][hh * 2] *= corr;
                oacc[dt][hh * 2 + 1] *= corr;
            }
        }

        // write P into warp-private A-frag region
#pragma unroll
        for (int nt = 0; nt < 8; ++nt)
#pragma unroll
            for (int e = 0; e < 4; ++e) {
                int kc = (tg << 1) + (e & 1);  // local key col 0..7
                int addr = ((w << 3) + nt) * 128 + (((g << 2) + (kc & 3)) << 2) +
                           (e >> 1) + ((kc >> 2) << 1);
                Ps[addr] = f2tf(sacc[nt][e]);
            }
        __syncwarp();

        // O += P @ V : warp tile m16 x n128, k=64
#pragma unroll
        for (int kt = 0; kt < 8; ++kt) {
            uint4 av = *(const uint4*)&Ps[((w << 3) + kt) * 128 + (lane << 2)];
#pragma unroll
            for (int dt = 0; dt < 16; ++dt) {
                uint2 bv =
                    *(const uint2*)&Vs[((dt << 3) + kt) * 64 + (lane << 1)];
                mma_tf32(oacc[dt], av.x, av.y, av.z, av.w, bv.x, bv.y);
            }
        }
    }

    // epilogue
#pragma unroll
    for (int hh = 0; hh < 2; ++hh) {
        float inv = 1.f / lrun[hh];
        int row = q0 + (w << 4) + g + (hh << 3);
#pragma unroll
        for (int dt = 0; dt < 16; ++dt) {
            float2 v = make_float2(oacc[dt][hh * 2] * inv,
                                   oacc[dt][hh * 2 + 1] * inv);
            *(float2*)&o[((size_t)(b * SS + row)) * DIM + h * HD + (dt << 3) +
                         (tg << 1)] = v;
        }
    }
}

// ---------------- launch ----------------
extern "C" void kernel_launch(void* const* d_in, const int* in_sizes, int n_in,
                              void* d_out, int out_size) {
    const float* x = (const float*)d_in[0];
    const float* prev_k = (const float*)d_in[1];
    const float* prev_v = (const float*)d_in[2];
    // d_in[3] = mask (computed analytically, unused)
    const float* wq = (const float*)d_in[4];
    const float* wk = (const float*)d_in[5];
    const float* wv = (const float*)d_in[6];
    const float* wo = (const float*)d_in[7];

    float* out = (float*)d_out;
    const size_t OUT_ELEMS = (size_t)BB * SS * DIM;
    const size_t KV_ELEMS = (size_t)BB * LL * NH * HD;

    float* xq;    cudaGetSymbolAddress((void**)&xq, g_xq);
    float* attn;  cudaGetSymbolAddress((void**)&attn, g_attn);
    float* kall;  cudaGetSymbolAddress((void**)&kall, g_kall);
    float* vall;  cudaGetSymbolAddress((void**)&vall, g_vall);

    // 1) history copy
    copy_hist_kernel<<<1024, 256>>>((const float4*)prev_k,
                                    (const float4*)prev_v, (float4*)kall,
                                    (float4*)vall);

    // 2) projections (tf32 mma)
    dim3 gproj(DIM / 128, (BB * SS) / 128);  // (16, 32)
    gemm_tf32_kernel<<<gproj, 256>>>(x, wq, xq, 0);
    gemm_tf32_kernel<<<gproj, 256>>>(x, wk, kall, 1);
    gemm_tf32_kernel<<<gproj, 256>>>(x, wv, vall, 1);

    // 3) attention (tf32 mma flash)
    cudaFuncSetAttribute(attn_mma_kernel,
                         cudaFuncAttributeMaxDynamicSharedMemorySize,
                         ATTN_SMEM_BYTES);
    attn_mma_kernel<<<dim3(SS / 128, NH, BB), 256, ATTN_SMEM_BYTES>>>(
        xq, kall, vall, attn);

    // 4) output projection
    gemm_tf32_kernel<<<gproj, 256>>>(attn, wo, out, 0);

    // 5) export k_all / v_all
    if ((size_t)out_size >= OUT_ELEMS + 2 * KV_ELEMS) {
        float* dk = out + OUT_ELEMS;
        float* dv = dk + KV_ELEMS;
        export_kv_kernel<<<2048, 256>>>((const float4*)kall,
                                        (const float4*)vall, (float4*)dk,
                                        (float4*)dv);
    }
}